// round 7
// baseline (speedup 1.0000x reference)
#include <cuda_runtime.h>
#include <cuda_bf16.h>
#include <cstdint>

// LinearAttentionCell with T=1 reduces algebraically to out = x @ Wv^T
// (memory = outer(k,v); mem_read = (q.k)*v; scale = (q.k) => out = v).
// bf16 HMMA (mma.sync m16n8k16) with 3-product Dekker splitting:
//   fp32 = hi + lo (bf16);  D += Ahi*Bhi + Ahi*Blo + Alo*Bhi  (fp32 accum)
// M=64 (batch) x N=2048 (out channels) x K=2048.
// R7: warp tile m16n16 (acc 8 regs), ~60 regs/thread, launch_bounds(256,4)
// -> 4 CTAs/SM, 8 warps/SMSP (2x latency hiding), no spills. Depth-2 W
// register prefetch, depth-2 A prefetch. No smem, no barriers.

#define KDIM 2048
#define NDIM 2048
#define MDIM 64
#define NT   32           // n per CTA
#define SPLITK 8
#define KCH  256          // k per CTA
#define KSTEPS_CTA 16     // KCH/16
#define GT   256          // 8 warps: 4 m16 x 2 n16

// x pre-split into mma A-fragment order:
// [mb(4)][ks_global(128)][lane(32)] -> uint4 (a0..a3)
__device__ __align__(16) uint4 g_ahi[4 * 128 * 32];
__device__ __align__(16) uint4 g_alo[4 * 128 * 32];

__device__ __forceinline__ uint32_t cvt2(float hi_e, float lo_e) {
    // packs: low 16 = bf16(lo_e), high 16 = bf16(hi_e)
    uint32_t r;
    asm("cvt.rn.bf16x2.f32 %0, %1, %2;" : "=r"(r) : "f"(hi_e), "f"(lo_e));
    return r;
}

// split a float2 (two consecutive k values) into one bf16x2 hi word + lo word
__device__ __forceinline__ void split2(float2 v, uint32_t& h, uint32_t& l) {
    h = cvt2(v.y, v.x);
    float f0 = __uint_as_float(h << 16);
    float f1 = __uint_as_float(h & 0xFFFF0000u);
    l = cvt2(v.y - f1, v.x - f0);
}

__device__ __forceinline__ void split4(float4 v, uint32_t& h01, uint32_t& h23,
                                       uint32_t& l01, uint32_t& l23) {
    split2(make_float2(v.x, v.y), h01, l01);
    split2(make_float2(v.z, v.w), h23, l23);
}

__device__ __forceinline__ void mma16816(float* d, const uint4& a,
                                         uint32_t b0, uint32_t b1) {
    asm volatile(
        "mma.sync.aligned.m16n8k16.row.col.f32.bf16.bf16.f32 "
        "{%0,%1,%2,%3}, {%4,%5,%6,%7}, {%8,%9}, {%0,%1,%2,%3};"
        : "+f"(d[0]), "+f"(d[1]), "+f"(d[2]), "+f"(d[3])
        : "r"(a.x), "r"(a.y), "r"(a.z), "r"(a.w), "r"(b0), "r"(b1));
}

// ---------------- kernel 1: x -> A-fragment hi/lo arrays ----------------
__global__ __launch_bounds__(256)
void convert_x_kernel(const float* __restrict__ x) {
    int t = blockIdx.x * 256 + threadIdx.x;   // 0..16383
    int mb   = t >> 12;
    int ks   = (t >> 5) & 127;
    int lane = t & 31;
    int g  = lane >> 2;
    int tt = lane & 3;
    int m0 = mb * 16 + g;
    int k0 = ks * 16 + 2 * tt;

    float2 p00 = *reinterpret_cast<const float2*>(&x[m0 * KDIM + k0]);
    float2 p10 = *reinterpret_cast<const float2*>(&x[(m0 + 8) * KDIM + k0]);
    float2 p01 = *reinterpret_cast<const float2*>(&x[m0 * KDIM + k0 + 8]);
    float2 p11 = *reinterpret_cast<const float2*>(&x[(m0 + 8) * KDIM + k0 + 8]);

    uint4 hi, lo;
    float4 v0 = make_float4(p00.x, p00.y, p10.x, p10.y);
    float4 v1 = make_float4(p01.x, p01.y, p11.x, p11.y);
    uint32_t h01, h23, l01, l23;
    split4(v0, h01, h23, l01, l23);
    hi.x = h01; hi.y = h23; lo.x = l01; lo.y = l23;
    split4(v1, h01, h23, l01, l23);
    hi.z = h01; hi.w = h23; lo.z = l01; lo.w = l23;

    g_ahi[t] = hi;
    g_alo[t] = lo;
}

// ---------------- kernel 2: smem-free HMMA GEMM, atomic split-K ----------------
__global__ __launch_bounds__(GT, 4)
void gemm_kernel(const float* __restrict__ Wv, float* __restrict__ out) {
    const int tid  = threadIdx.x;
    const int lane = tid & 31;
    const int wid  = tid >> 5;
    const int wm   = wid & 3;      // m16 group 0..3
    const int wn   = wid >> 2;     // n16 group 0..1
    const int g  = lane >> 2;
    const int tt = lane & 3;

    const int n0   = blockIdx.x * NT;
    const int ksg0 = blockIdx.y * KSTEPS_CTA;
    const int k0   = blockIdx.y * KCH;

    // A fragment pointers (pre-split, fragment order; stride 32 uint4 per k-step)
    const uint4* ahp = &g_ahi[(wm * 128 + ksg0) * 32 + lane];
    const uint4* alp = &g_alo[(wm * 128 + ksg0) * 32 + lane];

    // W fragment pointers: lane reads W[n0+wn*16+nf*8+g][k0+ks*16+tt*2 (+8)]
    const float* w0p = Wv + (size_t)(n0 + wn * 16 + 0 * 8 + g) * KDIM + k0 + tt * 2;
    const float* w1p = Wv + (size_t)(n0 + wn * 16 + 1 * 8 + g) * KDIM + k0 + tt * 2;

    float acc[2][4];
#pragma unroll
    for (int b = 0; b < 2; b++)
#pragma unroll
        for (int c = 0; c < 4; c++) acc[b][c] = 0.f;

    // depth-2 register prefetch buffers
    uint4  ahb[2], alb[2];
    float2 wa0b[2], wa1b[2], wb0b[2], wb1b[2];
#pragma unroll
    for (int s = 0; s < 2; s++) {
        ahb[s]  = ahp[s * 32];
        alb[s]  = alp[s * 32];
        wa0b[s] = *reinterpret_cast<const float2*>(w0p + s * 16);
        wa1b[s] = *reinterpret_cast<const float2*>(w0p + s * 16 + 8);
        wb0b[s] = *reinterpret_cast<const float2*>(w1p + s * 16);
        wb1b[s] = *reinterpret_cast<const float2*>(w1p + s * 16 + 8);
    }

#pragma unroll
    for (int ks = 0; ks < KSTEPS_CTA; ks++) {
        const int s = ks & 1;
        uint4 ah = ahb[s], al = alb[s];
        float2 wa0 = wa0b[s], wa1 = wa1b[s], wb0 = wb0b[s], wb1 = wb1b[s];

        int nx = (ks + 2 < KSTEPS_CTA) ? ks + 2 : ks;   // clamped dummy on tail
        ahb[s]  = ahp[nx * 32];
        alb[s]  = alp[nx * 32];
        wa0b[s] = *reinterpret_cast<const float2*>(w0p + nx * 16);
        wa1b[s] = *reinterpret_cast<const float2*>(w0p + nx * 16 + 8);
        wb0b[s] = *reinterpret_cast<const float2*>(w1p + nx * 16);
        wb1b[s] = *reinterpret_cast<const float2*>(w1p + nx * 16 + 8);

        // Dekker-split W in registers
        uint32_t bh00, bh01, bh10, bh11, bl00, bl01, bl10, bl11;
        split2(wa0, bh00, bl00);
        split2(wa1, bh01, bl01);
        split2(wb0, bh10, bl10);
        split2(wb1, bh11, bl11);

        // product-major: 2 independent accumulators between same-acc reuse
        mma16816(acc[0], ah, bh00, bh01);
        mma16816(acc[1], ah, bh10, bh11);
        mma16816(acc[0], ah, bl00, bl01);
        mma16816(acc[1], ah, bl10, bl11);
        mma16816(acc[0], al, bh00, bh01);
        mma16816(acc[1], al, bh10, bh11);
    }

    // epilogue: split-K combine via vector atomics into out
#pragma unroll
    for (int nf = 0; nf < 2; nf++) {
        int m = wm * 16 + g;
        int n = n0 + wn * 16 + nf * 8 + 2 * tt;
        atomicAdd(reinterpret_cast<float2*>(&out[m * NDIM + n]),
                  make_float2(acc[nf][0], acc[nf][1]));
        atomicAdd(reinterpret_cast<float2*>(&out[(m + 8) * NDIM + n]),
                  make_float2(acc[nf][2], acc[nf][3]));
    }
}

extern "C" void kernel_launch(void* const* d_in, const int* in_sizes, int n_in,
                              void* d_out, int out_size) {
    // inputs: 0=x [64,1,2048] f32, 1=Wq, 2=bq, 3=Wk, 4=bk, 5=Wv [2048,2048], 6=pos
    const float* x  = (const float*)d_in[0];
    const float* Wv = (const float*)d_in[5];
    float* out = (float*)d_out;

    cudaMemsetAsync(out, 0, (size_t)MDIM * NDIM * sizeof(float));
    convert_x_kernel<<<64, 256>>>(x);
    dim3 grid(NDIM / NT, SPLITK);   // 64 x 8 = 512 CTAs, 4 per SM
    gemm_kernel<<<grid, GT>>>(Wv, out);

    (void)in_sizes; (void)n_in; (void)out_size;
}

// round 8
// speedup vs baseline: 1.4767x; 1.4767x over previous
#include <cuda_runtime.h>
#include <cuda_bf16.h>
#include <cstdint>

// LinearAttentionCell with T=1 reduces algebraically to out = x @ Wv^T
// (memory = outer(k,v); mem_read = (q.k)*v; scale = (q.k) => out = v).
// bf16 HMMA (mma.sync m16n8k16) with 3-product Dekker splitting:
//   fp32 = hi + lo (bf16);  D += Ahi*Bhi + Ahi*Blo + Alo*Bhi  (fp32 accum)
// M=64 (batch) x N=2048 (out channels) x K=2048.
// R8: kill the L1 wavefront bottleneck. W goes through smem: dense LDG.128,
// register Dekker split, conflict-free swizzled STS of bf16 hi/lo tiles,
// then ldmatrix.m8n8.x4 (1 instruction = 4 B-fragments). A stays pre-split
// in global (L2-resident). Double-buffered 2-kstep stages, 1 barrier/stage.

#define KDIM 2048
#define NDIM 2048
#define MDIM 64
#define NT   64           // n per CTA
#define SPLITK 8
#define KCH  256          // k per CTA
#define NSTAGE 8          // KCH / 32
#define GT   256          // 8 warps: 2 wrow(m32) x 4 wcol(n16)

// x pre-split into mma A-fragment order:
// [mb(4)][ks_global(128)][lane(32)] -> uint4 (a0..a3)
__device__ __align__(16) uint4 g_ahi[4 * 128 * 32];
__device__ __align__(16) uint4 g_alo[4 * 128 * 32];

__device__ __forceinline__ uint32_t cvt2(float hi_e, float lo_e) {
    // packs: low 16 = bf16(lo_e), high 16 = bf16(hi_e)
    uint32_t r;
    asm("cvt.rn.bf16x2.f32 %0, %1, %2;" : "=r"(r) : "f"(hi_e), "f"(lo_e));
    return r;
}

__device__ __forceinline__ void split2(float2 v, uint32_t& h, uint32_t& l) {
    h = cvt2(v.y, v.x);
    float f0 = __uint_as_float(h << 16);
    float f1 = __uint_as_float(h & 0xFFFF0000u);
    l = cvt2(v.y - f1, v.x - f0);
}

__device__ __forceinline__ void split4(float4 v, uint32_t& h01, uint32_t& h23,
                                       uint32_t& l01, uint32_t& l23) {
    split2(make_float2(v.x, v.y), h01, l01);
    split2(make_float2(v.z, v.w), h23, l23);
}

__device__ __forceinline__ void mma16816(float* d, const uint4& a,
                                         uint32_t b0, uint32_t b1) {
    asm volatile(
        "mma.sync.aligned.m16n8k16.row.col.f32.bf16.bf16.f32 "
        "{%0,%1,%2,%3}, {%4,%5,%6,%7}, {%8,%9}, {%0,%1,%2,%3};"
        : "+f"(d[0]), "+f"(d[1]), "+f"(d[2]), "+f"(d[3])
        : "r"(a.x), "r"(a.y), "r"(a.z), "r"(a.w), "r"(b0), "r"(b1));
}

__device__ __forceinline__ void ldsm4(uint32_t* r, uint32_t addr) {
    asm volatile(
        "ldmatrix.sync.aligned.m8n8.x4.shared.b16 {%0,%1,%2,%3}, [%4];"
        : "=r"(r[0]), "=r"(r[1]), "=r"(r[2]), "=r"(r[3]) : "r"(addr));
}

// ---------------- kernel 1: x -> A-fragment hi/lo arrays + zero out ----------
__global__ __launch_bounds__(256)
void convert_x_kernel(const float* __restrict__ x, float4* __restrict__ outz) {
    int t = blockIdx.x * 256 + threadIdx.x;   // 0..16383
    // zero the output (atomic split-K target): 32768 float4, 2 per thread
    outz[t] = make_float4(0.f, 0.f, 0.f, 0.f);
    outz[t + 16384] = make_float4(0.f, 0.f, 0.f, 0.f);

    int mb   = t >> 12;
    int ks   = (t >> 5) & 127;
    int lane = t & 31;
    int g  = lane >> 2;
    int tt = lane & 3;
    int m0 = mb * 16 + g;
    int k0 = ks * 16 + 2 * tt;

    float2 p00 = *reinterpret_cast<const float2*>(&x[m0 * KDIM + k0]);
    float2 p10 = *reinterpret_cast<const float2*>(&x[(m0 + 8) * KDIM + k0]);
    float2 p01 = *reinterpret_cast<const float2*>(&x[m0 * KDIM + k0 + 8]);
    float2 p11 = *reinterpret_cast<const float2*>(&x[(m0 + 8) * KDIM + k0 + 8]);

    uint4 hi, lo;
    float4 v0 = make_float4(p00.x, p00.y, p10.x, p10.y);
    float4 v1 = make_float4(p01.x, p01.y, p11.x, p11.y);
    uint32_t h01, h23, l01, l23;
    split4(v0, h01, h23, l01, l23);
    hi.x = h01; hi.y = h23; lo.x = l01; lo.y = l23;
    split4(v1, h01, h23, l01, l23);
    hi.z = h01; hi.w = h23; lo.z = l01; lo.w = l23;

    g_ahi[t] = hi;
    g_alo[t] = lo;
}

// ---------------- kernel 2: smem-staged HMMA GEMM, atomic split-K -----------
__global__ __launch_bounds__(GT, 3)
void gemm_kernel(const float* __restrict__ Wv, float* __restrict__ out) {
    // bf16 tiles: [buf][kstep][64 rows x 16 k], 2KB each, XOR-swizzled 16B chunks
    __shared__ __align__(16) uint8_t SH[2][2][2048];
    __shared__ __align__(16) uint8_t SL[2][2][2048];

    const int tid  = threadIdx.x;
    const int lane = tid & 31;
    const int wid  = tid >> 5;
    const int wrow = wid >> 2;     // m32 group 0..1
    const int wcol = wid & 3;      // n16 group 0..3
    const int g  = lane >> 2;
    const int tt = lane & 3;

    const int n0   = blockIdx.x * NT;
    const int k0   = blockIdx.y * KCH;
    const int ksg0 = blockIdx.y * (KCH / 16);

    // ---- W staging mapping: thread -> (row, 4-float k chunk) ----
    const int r  = tid >> 2;           // 0..63
    const int kq = (tid & 3) * 4;      // float offset within 16-float kstep
    const int h  = kq >> 3;            // k-half (0: k0-7, 1: k8-15)
    const int off8 = (kq & 4) ? 8 : 0;
    const int sts_off = r * 32 + (((h ^ (r >> 2)) & 1) << 4) + off8;
    const float* wptr = Wv + (size_t)(n0 + r) * KDIM + k0 + kq;

    // ---- ldmatrix lane address (per 2KB tile) ----
    const int nl   = ((lane >> 4) & 1) * 8 + (lane & 7);
    const int hh   = (lane >> 3) & 1;
    const int brow = wcol * 16 + nl;
    const int ldsm_off = brow * 32 + (((hh ^ (brow >> 2)) & 1) << 4);

    // ---- A fragment pointers (pre-split global, fragment order) ----
    const uint4* ah0p = &g_ahi[((wrow * 2 + 0) * 128 + ksg0) * 32 + lane];
    const uint4* al0p = &g_alo[((wrow * 2 + 0) * 128 + ksg0) * 32 + lane];
    const uint4* ah1p = &g_ahi[((wrow * 2 + 1) * 128 + ksg0) * 32 + lane];
    const uint4* al1p = &g_alo[((wrow * 2 + 1) * 128 + ksg0) * 32 + lane];

    float acc[2][2][4];
#pragma unroll
    for (int a = 0; a < 2; a++)
#pragma unroll
        for (int b = 0; b < 2; b++)
#pragma unroll
            for (int c = 0; c < 4; c++) acc[a][b][c] = 0.f;

    // prologue: load stage 0 W registers (kstep0 floats kq..kq+3, kstep1 +16)
    float4 wA = *reinterpret_cast<const float4*>(wptr);
    float4 wB = *reinterpret_cast<const float4*>(wptr + 16);

#pragma unroll
    for (int s = 0; s < NSTAGE; s++) {
        const int buf = s & 1;
        // split + store both ksteps of this stage
        {
            uint32_t h01, h23, l01, l23;
            split4(wA, h01, h23, l01, l23);
            *reinterpret_cast<uint2*>(&SH[buf][0][sts_off]) = make_uint2(h01, h23);
            *reinterpret_cast<uint2*>(&SL[buf][0][sts_off]) = make_uint2(l01, l23);
            split4(wB, h01, h23, l01, l23);
            *reinterpret_cast<uint2*>(&SH[buf][1][sts_off]) = make_uint2(h01, h23);
            *reinterpret_cast<uint2*>(&SL[buf][1][sts_off]) = make_uint2(l01, l23);
        }
        __syncthreads();

        if (s + 1 < NSTAGE) {   // prefetch next stage (overlaps MMAs)
            wA = *reinterpret_cast<const float4*>(wptr + (s + 1) * 32);
            wB = *reinterpret_cast<const float4*>(wptr + (s + 1) * 32 + 16);
        }

#pragma unroll
        for (int ks = 0; ks < 2; ks++) {
            const int kidx = (s * 2 + ks) * 32;
            uint4 ah0 = ah0p[kidx], al0 = al0p[kidx];
            uint4 ah1 = ah1p[kidx], al1 = al1p[kidx];

            uint32_t bh[4], bl[4];
            ldsm4(bh, (uint32_t)__cvta_generic_to_shared(&SH[buf][ks][0]) + ldsm_off);
            ldsm4(bl, (uint32_t)__cvta_generic_to_shared(&SL[buf][ks][0]) + ldsm_off);

            // product-major: 4 independent accumulators between same-acc reuse
            mma16816(acc[0][0], ah0, bh[0], bh[1]);
            mma16816(acc[0][1], ah0, bh[2], bh[3]);
            mma16816(acc[1][0], ah1, bh[0], bh[1]);
            mma16816(acc[1][1], ah1, bh[2], bh[3]);

            mma16816(acc[0][0], ah0, bl[0], bl[1]);
            mma16816(acc[0][1], ah0, bl[2], bl[3]);
            mma16816(acc[1][0], ah1, bl[0], bl[1]);
            mma16816(acc[1][1], ah1, bl[2], bl[3]);

            mma16816(acc[0][0], al0, bh[0], bh[1]);
            mma16816(acc[0][1], al0, bh[2], bh[3]);
            mma16816(acc[1][0], al1, bh[0], bh[1]);
            mma16816(acc[1][1], al1, bh[2], bh[3]);
        }
    }

    // epilogue: split-K combine via vector atomics into out
#pragma unroll
    for (int mb = 0; mb < 2; mb++) {
#pragma unroll
        for (int nf = 0; nf < 2; nf++) {
            int m = (wrow * 2 + mb) * 16 + g;
            int n = n0 + wcol * 16 + nf * 8 + 2 * tt;
            atomicAdd(reinterpret_cast<float2*>(&out[m * NDIM + n]),
                      make_float2(acc[mb][nf][0], acc[mb][nf][1]));
            atomicAdd(reinterpret_cast<float2*>(&out[(m + 8) * NDIM + n]),
                      make_float2(acc[mb][nf][2], acc[mb][nf][3]));
        }
    }
}

extern "C" void kernel_launch(void* const* d_in, const int* in_sizes, int n_in,
                              void* d_out, int out_size) {
    // inputs: 0=x [64,1,2048] f32, 1=Wq, 2=bq, 3=Wk, 4=bk, 5=Wv [2048,2048], 6=pos
    const float* x  = (const float*)d_in[0];
    const float* Wv = (const float*)d_in[5];
    float* out = (float*)d_out;

    convert_x_kernel<<<64, 256>>>(x, (float4*)out);
    dim3 grid(NDIM / NT, SPLITK);   // 32 x 8 = 256 CTAs, 3 per SM
    gemm_kernel<<<grid, GT>>>(Wv, out);

    (void)in_sizes; (void)n_in; (void)out_size;
}